// round 11
// baseline (speedup 1.0000x reference)
#include <cuda_runtime.h>
#include <cuda_fp16.h>
#include <stdint.h>

#define NUM_SEGMENTS 4480
#define ATOM_DIM 64
#define BOND_DIM 16
#define N_EDGES 65536
#define YSTRIDE 1152   // padded row stride (halves)
#define CAP 64         // max edges per src bucket (lambda=14.6, P(>64)~1e-20)
#define S_PER_BLK 8    // src atoms per edge-block

// Scratch
__device__ __half g_Yh[(size_t)NUM_SEGMENTS * YSTRIDE];
__device__ int    g_cursor[NUM_SEGMENTS];
__device__ int    g_pk[NUM_SEGMENTS * CAP];   // (dst<<16) | eid

// ---- tensor-core helpers ----
__device__ __forceinline__ uint32_t smem_u32(const void* p) {
    return (uint32_t)__cvta_generic_to_shared(p);
}
__device__ __forceinline__ void ldm_x4(uint32_t& r0, uint32_t& r1,
                                       uint32_t& r2, uint32_t& r3, uint32_t addr) {
    asm volatile("ldmatrix.sync.aligned.m8n8.x4.shared.b16 {%0,%1,%2,%3}, [%4];"
                 : "=r"(r0), "=r"(r1), "=r"(r2), "=r"(r3) : "r"(addr));
}
__device__ __forceinline__ void mma16816(float* c,
                                         uint32_t a0, uint32_t a1, uint32_t a2, uint32_t a3,
                                         uint32_t b0, uint32_t b1) {
    asm volatile("mma.sync.aligned.m16n8k16.row.col.f32.f16.f16.f32 "
                 "{%0,%1,%2,%3}, {%4,%5,%6,%7}, {%8,%9}, {%0,%1,%2,%3};"
                 : "+f"(c[0]), "+f"(c[1]), "+f"(c[2]), "+f"(c[3])
                 : "r"(a0), "r"(a1), "r"(a2), "r"(a3), "r"(b0), "r"(b1));
}

#define AH_STRIDE 72
#define BS_STRIDE 72

// ---------------------------------------------------------------------------
// Phase 1 (tensor cores): Y = atom (4480x64) @ W (64x1088) -> fp16 (stride 1152).
// R10-validated structure. y==0 blocks zero `out`; y==1 blocks zero g_cursor.
// ---------------------------------------------------------------------------
__global__ void __launch_bounds__(256)
proj_kernel(const float* __restrict__ atom,
            const float* __restrict__ kern,
            const float* __restrict__ bias,
            float* __restrict__ out)
{
    __shared__ __align__(16) __half Ah[128 * AH_STRIDE];
    __shared__ __align__(16) __half Bs[128 * BS_STRIDE];

    const int a0  = blockIdx.x * 128;   // 35 blocks
    const int c0g = blockIdx.y * 128;   // 9 blocks
    const int tid = threadIdx.x;

    if (blockIdx.y == 0) {
        float4* oz = (float4*)(out + (size_t)a0 * 64);
        #pragma unroll
        for (int t = 0; t < 8; t++)
            oz[tid + t * 256] = make_float4(0.f, 0.f, 0.f, 0.f);
    } else if (blockIdx.y == 1) {
        int i = blockIdx.x * 256 + tid;     // 8960 >= 4480
        if (i < NUM_SEGMENTS) g_cursor[i] = 0;
    }

    #pragma unroll
    for (int t = 0; t < 8; t++) {
        int idx = tid + t * 256;
        int r = idx >> 4, f4 = idx & 15;
        float4 v = *(const float4*)(atom + (size_t)(a0 + r) * 64 + f4 * 4);
        __half2 h01 = __floats2half2_rn(v.x, v.y);
        __half2 h23 = __floats2half2_rn(v.z, v.w);
        *(uint2*)&Ah[r * AH_STRIDE + f4 * 4] =
            make_uint2(*(uint32_t*)&h01, *(uint32_t*)&h23);
    }
    #pragma unroll
    for (int t = 0; t < 8; t++) {
        int idx = tid + t * 256;
        int c = idx >> 4, f4 = idx & 15;
        int gc = c0g + c;
        float4 v = make_float4(0.f, 0.f, 0.f, 0.f);
        if (gc < 1024) {
            int kk = gc >> 6, i = gc & 63;
            v = *(const float4*)(kern + kk * 4096 + i * 64 + f4 * 4);
        } else if (gc < 1088) {
            v = *(const float4*)(bias + (gc - 1024) * 64 + f4 * 4);
        }
        __half2 h01 = __floats2half2_rn(v.x, v.y);
        __half2 h23 = __floats2half2_rn(v.z, v.w);
        *(uint2*)&Bs[c * BS_STRIDE + f4 * 4] =
            make_uint2(*(uint32_t*)&h01, *(uint32_t*)&h23);
    }
    __syncthreads();

    const int wid  = tid >> 5;
    const int lane = tid & 31;
    const int m0   = wid * 16;

    uint32_t Af[4][4];
    {
        const uint32_t a_base =
            smem_u32(&Ah[(m0 + (lane & 15)) * AH_STRIDE + ((lane >> 4) << 3)]);
        #pragma unroll
        for (int ks = 0; ks < 4; ks++)
            ldm_x4(Af[ks][0], Af[ks][1], Af[ks][2], Af[ks][3], a_base + ks * 32);
    }

    const int r  = lane >> 2;
    const int cp = (lane & 3) * 2;

    #pragma unroll
    for (int h = 0; h < 2; h++) {
        const uint32_t b_base =
            smem_u32(&Bs[(h * 64 + ((lane >> 4) << 3) + (lane & 7)) * BS_STRIDE +
                         (((lane >> 3) & 1) << 3)]);

        float acc[8][4] = {};
        #pragma unroll
        for (int ks = 0; ks < 4; ks++) {
            #pragma unroll
            for (int nss = 0; nss < 4; nss++) {
                uint32_t B0, B1, B2, B3;
                ldm_x4(B0, B1, B2, B3,
                       b_base + nss * 16 * BS_STRIDE * 2 + ks * 32);
                mma16816(acc[2 * nss],     Af[ks][0], Af[ks][1], Af[ks][2], Af[ks][3], B0, B1);
                mma16816(acc[2 * nss + 1], Af[ks][0], Af[ks][1], Af[ks][2], Af[ks][3], B2, B3);
            }
        }

        const int colbase = c0g + h * 64;
        #pragma unroll
        for (int s = 0; s < 8; s++) {
            const int col = colbase + s * 8 + cp;
            const size_t row0 = (size_t)(a0 + m0 + r);
            *(__half2*)&g_Yh[row0 * YSTRIDE + col]       = __floats2half2_rn(acc[s][0], acc[s][1]);
            *(__half2*)&g_Yh[(row0 + 8) * YSTRIDE + col] = __floats2half2_rn(acc[s][2], acc[s][3]);
        }
    }
}

// ---------------------------------------------------------------------------
// Phase 2a: bucket edges by src, 4 edges/thread (atomic MLP=4).
// ---------------------------------------------------------------------------
__global__ void __launch_bounds__(256)
scatter_kernel(const int* __restrict__ pair)
{
    const int t = blockIdx.x * 256 + threadIdx.x;   // 16384 threads
    const int2 p0 = ((const int2*)pair)[t];
    const int2 p1 = ((const int2*)pair)[t + 16384];
    const int2 p2 = ((const int2*)pair)[t + 32768];
    const int2 p3 = ((const int2*)pair)[t + 49152];
    const int pos0 = atomicAdd(&g_cursor[p0.y], 1);
    const int pos1 = atomicAdd(&g_cursor[p1.y], 1);
    const int pos2 = atomicAdd(&g_cursor[p2.y], 1);
    const int pos3 = atomicAdd(&g_cursor[p3.y], 1);
    if (pos0 < CAP) g_pk[p0.y * CAP + pos0] = (p0.x << 16) | t;
    if (pos1 < CAP) g_pk[p1.y * CAP + pos1] = (p1.x << 16) | (t + 16384);
    if (pos2 < CAP) g_pk[p2.y * CAP + pos2] = (p2.x << 16) | (t + 32768);
    if (pos3 < CAP) g_pk[p3.y * CAP + pos3] = (p3.x << 16) | (t + 49152);
}

// ---------------------------------------------------------------------------
// Phase 2b: half-warp per edge (SAME body as the validated 13.8us kernel),
// but a block processes the bucketed edges of 8 src atoms -> Y rows stay in L1.
// ---------------------------------------------------------------------------
__global__ void __launch_bounds__(256)
edge_kernel(const float* __restrict__ bond,
            float* __restrict__ out)
{
    __shared__ int s_off[S_PER_BLK + 1];
    const int tid = threadIdx.x;
    const int s0  = blockIdx.x * S_PER_BLK;   // 560 blocks

    if (tid == 0) {
        int run = 0;
        #pragma unroll
        for (int i = 0; i < S_PER_BLK; i++) {
            s_off[i] = run;
            int d = g_cursor[s0 + i];
            run += (d > CAP) ? CAP : d;
        }
        s_off[S_PER_BLK] = run;
    }
    __syncthreads();
    const int T = s_off[S_PER_BLK];

    const int hw  = tid >> 4;   // half-warp id 0..15
    const int lid = tid & 15;

    for (int w = hw; w < T; w += 16) {
        int si = 0;
        #pragma unroll
        for (int i = 1; i < S_PER_BLK; i++) si += (w >= s_off[i]);
        const int src  = s0 + si;
        const int pk   = g_pk[src * CAP + (w - s_off[si])];
        const int eid  = pk & 0xffff;
        const int dst  = pk >> 16;

        const float4* __restrict__ bp = (const float4*)(bond + (size_t)eid * 16);
        const float4 q0 = __ldg(bp + 0);
        const float4 q1 = __ldg(bp + 1);
        const float4 q2 = __ldg(bp + 2);
        const float4 q3 = __ldg(bp + 3);
        const float bk[16] = {q0.x, q0.y, q0.z, q0.w,
                              q1.x, q1.y, q1.z, q1.w,
                              q2.x, q2.y, q2.z, q2.w,
                              q3.x, q3.y, q3.z, q3.w};

        const __half* __restrict__ y = g_Yh + (size_t)src * YSTRIDE + 4 * lid;

        float m0, m1, m2, m3;
        {
            const uint2 v = *(const uint2*)(y + 1024);
            const float2 flo = __half22float2(*(const __half2*)&v.x);
            const float2 fhi = __half22float2(*(const __half2*)&v.y);
            m0 = flo.x; m1 = flo.y; m2 = fhi.x; m3 = fhi.y;
        }
        #pragma unroll
        for (int k = 0; k < 16; k++) {
            const uint2 v = *(const uint2*)(y + k * 64);
            const float2 flo = __half22float2(*(const __half2*)&v.x);
            const float2 fhi = __half22float2(*(const __half2*)&v.y);
            const float b = bk[k];
            m0 = fmaf(b, flo.x, m0);
            m1 = fmaf(b, flo.y, m1);
            m2 = fmaf(b, fhi.x, m2);
            m3 = fmaf(b, fhi.y, m3);
        }

        float* o = out + (size_t)dst * 64 + 4 * lid;
        asm volatile("red.global.add.v4.f32 [%0], {%1, %2, %3, %4};"
                     :: "l"(o), "f"(m0), "f"(m1), "f"(m2), "f"(m3)
                     : "memory");
    }
}

extern "C" void kernel_launch(void* const* d_in, const int* in_sizes, int n_in,
                              void* d_out, int out_size)
{
    const float* atom = (const float*)d_in[0];      // [4480, 64]
    const float* bond = (const float*)d_in[1];      // [65536, 16]
    const int*   pair = (const int*)d_in[2];        // [65536, 2] int32
    const float* kern = (const float*)d_in[3];      // [16, 4096]
    const float* bias = (const float*)d_in[4];      // [4096]
    float*       out  = (float*)d_out;              // [4480, 64]

    (void)in_sizes; (void)n_in; (void)out_size;

    dim3 grid1(NUM_SEGMENTS / 128, 9);  // y==0 zeroes out, y==1 zeroes cursors
    proj_kernel<<<grid1, 256>>>(atom, kern, bias, out);

    scatter_kernel<<<64, 256>>>(pair);

    edge_kernel<<<NUM_SEGMENTS / S_PER_BLK, 256>>>(bond, out);
}

// round 12
// speedup vs baseline: 1.5007x; 1.5007x over previous
#include <cuda_runtime.h>
#include <cuda_fp16.h>
#include <stdint.h>

#define NUM_SEGMENTS 4480
#define ATOM_DIM 64
#define BOND_DIM 16
#define N_EDGES 65536
#define YSTRIDE 1152   // padded row stride (halves): 1024 kernel cols + 64 bias + 64 pad

// Scratch: per-atom projected features in fp16, padded stride.
__device__ __half g_Yh[(size_t)NUM_SEGMENTS * YSTRIDE];

// ---- tensor-core helpers ----
__device__ __forceinline__ uint32_t smem_u32(const void* p) {
    return (uint32_t)__cvta_generic_to_shared(p);
}
__device__ __forceinline__ void ldm_x4(uint32_t& r0, uint32_t& r1,
                                       uint32_t& r2, uint32_t& r3, uint32_t addr) {
    asm volatile("ldmatrix.sync.aligned.m8n8.x4.shared.b16 {%0,%1,%2,%3}, [%4];"
                 : "=r"(r0), "=r"(r1), "=r"(r2), "=r"(r3) : "r"(addr));
}
__device__ __forceinline__ void mma16816(float* c,
                                         uint32_t a0, uint32_t a1, uint32_t a2, uint32_t a3,
                                         uint32_t b0, uint32_t b1) {
    asm volatile("mma.sync.aligned.m16n8k16.row.col.f32.f16.f16.f32 "
                 "{%0,%1,%2,%3}, {%4,%5,%6,%7}, {%8,%9}, {%0,%1,%2,%3};"
                 : "+f"(c[0]), "+f"(c[1]), "+f"(c[2]), "+f"(c[3])
                 : "r"(a0), "r"(a1), "r"(a2), "r"(a3), "r"(b0), "r"(b1));
}

#define AH_STRIDE 72
#define BS_STRIDE 72

// ---------------------------------------------------------------------------
// Phase 1 (tensor cores): Y = atom (4480x64) @ W (64x1088) -> fp16 (stride 1152).
//   W[j][c] = kernel[(c>>6)*4096 + (c&63)*64 + j]  (c<1024)
//   W[j][1024+i] = bias[i*64 + j];  W[j][c>=1088] = 0 (stored to padding)
// Tile 64(M) x 128(N), grid (70, 9) = 630 blocks for occupancy.
// 8 warps: warp w -> rows (w&3)*16, col-half (w>>2)*64 (16x64 strip, 32 MMAs).
// y==0 blocks also zero `out`.
// ---------------------------------------------------------------------------
__global__ void __launch_bounds__(256)
proj_kernel(const float* __restrict__ atom,
            const float* __restrict__ kern,
            const float* __restrict__ bias,
            float* __restrict__ out)
{
    __shared__ __align__(16) __half Ah[64 * AH_STRIDE];    // 9 KB
    __shared__ __align__(16) __half Bs[128 * BS_STRIDE];   // 18 KB

    const int a0  = blockIdx.x * 64;    // 70 blocks
    const int c0g = blockIdx.y * 128;   // 9 blocks (last: 1024..1151, tail padded)
    const int tid = threadIdx.x;

    if (blockIdx.y == 0) {
        float4* oz = (float4*)(out + (size_t)a0 * 64);
        // 64 rows * 64 cols = 4096 floats = 1024 float4
        #pragma unroll
        for (int t = 0; t < 4; t++)
            oz[tid + t * 256] = make_float4(0.f, 0.f, 0.f, 0.f);
    }

    // Fill Ah[r][j] from atom via float4 (4 iters)
    #pragma unroll
    for (int t = 0; t < 4; t++) {
        int idx = tid + t * 256;          // 1024 float4s: r = idx/16, f4 = idx%16
        int r = idx >> 4, f4 = idx & 15;
        float4 v = *(const float4*)(atom + (size_t)(a0 + r) * 64 + f4 * 4);
        __half2 h01 = __floats2half2_rn(v.x, v.y);
        __half2 h23 = __floats2half2_rn(v.z, v.w);
        *(uint2*)&Ah[r * AH_STRIDE + f4 * 4] =
            make_uint2(*(uint32_t*)&h01, *(uint32_t*)&h23);
    }
    // Fill Bs[c][j] = W[j][c0g+c] for c in 0..127 via float4 (8 iters)
    #pragma unroll
    for (int t = 0; t < 8; t++) {
        int idx = tid + t * 256;          // 2048 float4s: c = idx/16, f4 = idx%16
        int c = idx >> 4, f4 = idx & 15;
        int gc = c0g + c;
        float4 v = make_float4(0.f, 0.f, 0.f, 0.f);
        if (gc < 1024) {
            int kk = gc >> 6, i = gc & 63;
            v = *(const float4*)(kern + kk * 4096 + i * 64 + f4 * 4);
        } else if (gc < 1088) {
            v = *(const float4*)(bias + (gc - 1024) * 64 + f4 * 4);
        }
        __half2 h01 = __floats2half2_rn(v.x, v.y);
        __half2 h23 = __floats2half2_rn(v.z, v.w);
        *(uint2*)&Bs[c * BS_STRIDE + f4 * 4] =
            make_uint2(*(uint32_t*)&h01, *(uint32_t*)&h23);
    }
    __syncthreads();

    const int wid  = tid >> 5;
    const int lane = tid & 31;
    const int m0   = (wid & 3) * 16;   // row group
    const int ch   = wid >> 2;         // col half (0 or 1)

    // Hoisted A fragments
    uint32_t Af[4][4];
    {
        const uint32_t a_base =
            smem_u32(&Ah[(m0 + (lane & 15)) * AH_STRIDE + ((lane >> 4) << 3)]);
        #pragma unroll
        for (int ks = 0; ks < 4; ks++)
            ldm_x4(Af[ks][0], Af[ks][1], Af[ks][2], Af[ks][3], a_base + ks * 32);
    }

    const uint32_t b_base =
        smem_u32(&Bs[(ch * 64 + ((lane >> 4) << 3) + (lane & 7)) * BS_STRIDE +
                     (((lane >> 3) & 1) << 3)]);

    float acc[8][4] = {};
    #pragma unroll
    for (int ks = 0; ks < 4; ks++) {
        #pragma unroll
        for (int nss = 0; nss < 4; nss++) {
            uint32_t B0, B1, B2, B3;
            ldm_x4(B0, B1, B2, B3,
                   b_base + nss * 16 * BS_STRIDE * 2 + ks * 32);
            mma16816(acc[2 * nss],     Af[ks][0], Af[ks][1], Af[ks][2], Af[ks][3], B0, B1);
            mma16816(acc[2 * nss + 1], Af[ks][0], Af[ks][1], Af[ks][2], Af[ks][3], B2, B3);
        }
    }

    const int r  = lane >> 2;
    const int cp = (lane & 3) * 2;
    const int colbase = c0g + ch * 64;
    #pragma unroll
    for (int s = 0; s < 8; s++) {
        const int col = colbase + s * 8 + cp;
        const size_t row0 = (size_t)(a0 + m0 + r);
        *(__half2*)&g_Yh[row0 * YSTRIDE + col]       = __floats2half2_rn(acc[s][0], acc[s][1]);
        *(__half2*)&g_Yh[(row0 + 8) * YSTRIDE + col] = __floats2half2_rn(acc[s][2], acc[s][3]);
    }
}

// ---------------------------------------------------------------------------
// Phase 2: half-warp per edge (validated 13.8us structure, unchanged).
// Lane lid handles output features 4*lid..4*lid+3.
// ---------------------------------------------------------------------------
__global__ void __launch_bounds__(256)
edge_kernel(const float* __restrict__ bond,
            const int* __restrict__ pair,
            float* __restrict__ out)
{
    const int warp = blockIdx.x * 8 + (threadIdx.x >> 5);
    const int half = (threadIdx.x >> 4) & 1;
    const int lid  = threadIdx.x & 15;
    const int e = warp * 2 + half;

    const int2 pr = ((const int2*)pair)[e];
    const int dst = pr.x;
    const int src = pr.y;

    const float4* __restrict__ bp = (const float4*)(bond + (size_t)e * 16);
    const float4 q0 = __ldg(bp + 0);
    const float4 q1 = __ldg(bp + 1);
    const float4 q2 = __ldg(bp + 2);
    const float4 q3 = __ldg(bp + 3);
    const float bk[16] = {q0.x, q0.y, q0.z, q0.w,
                          q1.x, q1.y, q1.z, q1.w,
                          q2.x, q2.y, q2.z, q2.w,
                          q3.x, q3.y, q3.z, q3.w};

    const __half* __restrict__ y = g_Yh + (size_t)src * YSTRIDE + 4 * lid;

    float m0, m1, m2, m3;
    {
        const uint2 v = *(const uint2*)(y + 1024);
        const float2 flo = __half22float2(*(const __half2*)&v.x);
        const float2 fhi = __half22float2(*(const __half2*)&v.y);
        m0 = flo.x; m1 = flo.y; m2 = fhi.x; m3 = fhi.y;
    }

    #pragma unroll
    for (int k = 0; k < 16; k++) {
        const uint2 v = *(const uint2*)(y + k * 64);
        const float2 flo = __half22float2(*(const __half2*)&v.x);
        const float2 fhi = __half22float2(*(const __half2*)&v.y);
        const float b = bk[k];
        m0 = fmaf(b, flo.x, m0);
        m1 = fmaf(b, flo.y, m1);
        m2 = fmaf(b, fhi.x, m2);
        m3 = fmaf(b, fhi.y, m3);
    }

    float* o = out + (size_t)dst * 64 + 4 * lid;
    asm volatile("red.global.add.v4.f32 [%0], {%1, %2, %3, %4};"
                 :: "l"(o), "f"(m0), "f"(m1), "f"(m2), "f"(m3)
                 : "memory");
}

extern "C" void kernel_launch(void* const* d_in, const int* in_sizes, int n_in,
                              void* d_out, int out_size)
{
    const float* atom = (const float*)d_in[0];      // [4480, 64]
    const float* bond = (const float*)d_in[1];      // [65536, 16]
    const int*   pair = (const int*)d_in[2];        // [65536, 2] int32
    const float* kern = (const float*)d_in[3];      // [16, 4096]
    const float* bias = (const float*)d_in[4];      // [4096]
    float*       out  = (float*)d_out;              // [4480, 64]

    (void)in_sizes; (void)n_in; (void)out_size;

    dim3 grid1(NUM_SEGMENTS / 64, 9);  // (70, 9); y==0 blocks zero `out`
    proj_kernel<<<grid1, 256>>>(atom, kern, bias, out);

    edge_kernel<<<N_EDGES / 16, 256>>>(bond, pair, out);
}